// round 13
// baseline (speedup 1.0000x reference)
#include <cuda_runtime.h>
#include <cuda_fp16.h>
#include <math.h>
#include <float.h>

#define B_DIM  256
#define T_DIM  150
#define J_DIM  25
#define FEAT   9
#define NACC   7
#define SPLIT  5
#define TCHUNK (T_DIM / SPLIT)          // 30 timesteps per block
#define NPAIR  (TCHUNK / 2)             // 15 timestep-pairs
#define TPB    (NPAIR * J_DIM)          // 375 threads; thread = (pair, joint)
#define OUTB   (J_DIM * FEAT)           // 225
#define PARTB  (J_DIM * NACC)           // 175

__device__ float    g_scratch[B_DIM][SPLIT][PARTB];
__device__ unsigned g_ticket[B_DIM];    // zero-init; self-resetting

__device__ __forceinline__ float asqrt(float x) {
    float r;
    asm("sqrt.approx.f32 %0, %1;" : "=f"(r) : "f"(x));
    return r;
}

__global__ __launch_bounds__(TPB)
void knn_feat_kernel(const float* __restrict__ x, float* __restrict__ out) {
    // packed positions: flat[tid] = {x2, y2, z2, pad}; half2 lanes = (t, t+15)
    __shared__ uint4 sq[NPAIR][J_DIM];       // 6000 B
    __shared__ float spart[PARTB];
    __shared__ float sfin[PARTB];
    __shared__ bool  s_last;

    const int b   = blockIdx.x;
    const int s   = blockIdx.y;
    const int tid = threadIdx.x;

    // lean prologue: thread tid owns smem entry tid = pr*25 + jidx,
    // which packs items tid (t = pr) and tid + 375 (t = pr + 15).
    {
        const float* xb = x + ((size_t)b * T_DIM + s * TCHUNK) * (J_DIM * 3);
        const float* p0 = xb + 3 * tid;            // item (pr, jidx)
        const float* p1 = xb + 3 * (tid + TPB);    // item (pr+15, jidx)
        __half2 X = __floats2half2_rn(p0[0], p1[0]);   // one cvt.rn.f16x2.f32
        __half2 Y = __floats2half2_rn(p0[1], p1[1]);
        __half2 Z = __floats2half2_rn(p0[2], p1[2]);
        uint4 v;
        v.x = *(unsigned*)&X;
        v.y = *(unsigned*)&Y;
        v.z = *(unsigned*)&Z;
        v.w = 0u;
        ((uint4*)sq)[tid] = v;                     // one STS.128
    }
    if (tid < PARTB) spart[tid] = 0.0f;
    __syncthreads();

    const int jidx = tid % J_DIM;            // this thread's joint
    const int pr   = tid / J_DIM;            // timestep pair (0..14)

    // query position (both halves) — one LDS.128
    const uint4 P = sq[pr][jidx];
    const __half2 px = *(const __half2*)&P.x;
    const __half2 py = *(const __half2*)&P.y;
    const __half2 pz = *(const __half2*)&P.z;

    const unsigned inf_bits = 0x7C007C00u;   // (+inf, +inf)
    const __half2 inf2 = *(const __half2*)&inf_bits;

    __half2 m0 = inf2, m1 = inf2, m2 = inf2, m3 = inf2;

#pragma unroll
    for (int j = 0; j < J_DIM; ++j) {
        const uint4 Q = sq[pr][j];           // broadcast LDS.128, feeds 2 candidates
        const __half2 qx = *(const __half2*)&Q.x;
        const __half2 qy = *(const __half2*)&Q.y;
        const __half2 qz = *(const __half2*)&Q.z;

        const __half2 dx = __hsub2(px, qx);
        const __half2 dy = __hsub2(py, qy);
        const __half2 dz = __hsub2(pz, qz);
        __half2 g = __hfma2(dx, dx, __hfma2(dy, dy, __hmul2(dz, dz)));
        g = (j == jidx) ? inf2 : g;          // mask self (both halves)

        __half2 h;
        h = __hmax2(g, m0); m0 = __hmin2(g, m0); g = h;
        h = __hmax2(g, m1); m1 = __hmin2(g, m1); g = h;
        h = __hmax2(g, m2); m2 = __hmin2(g, m2); g = h;
        m3 = __hmin2(g, m3);
    }

    // epilogue: two chains (lo/hi halves), features in fp32, summed
    float S1 = 0.f, S2 = 0.f, S3 = 0.f, S4 = 0.f;
    float V2 = 0.f, V3 = 0.f, V4 = 0.f;

#pragma unroll
    for (int h = 0; h < 2; ++h) {
        const float q0 = h ? __high2float(m0) : __low2float(m0);
        const float q1 = h ? __high2float(m1) : __low2float(m1);
        const float q2 = h ? __high2float(m2) : __low2float(m2);
        const float q3 = h ? __high2float(m3) : __low2float(m3);

        const float d1 = asqrt(q0);
        const float d2 = asqrt(q1);
        const float d3 = asqrt(q2);
        const float d4 = asqrt(q3);

        const float s2 = fabsf(d2 - d1) * 0.70710678118654752f;
        const float a3 = (d1 + d2 + d3) * (1.0f / 3.0f);
        const float e1 = d1 - a3, e2 = d2 - a3, e3 = d3 - a3;
        const float s3 = asqrt(fmaf(e1, e1, fmaf(e2, e2, e3 * e3)) * 0.5f);
        const float a4 = (d1 + d2 + d3 + d4) * 0.25f;
        const float g1 = d1 - a4, g2 = d2 - a4, g3 = d3 - a4, g4 = d4 - a4;
        const float s4 = asqrt(fmaf(g1, g1, fmaf(g2, g2, fmaf(g3, g3, g4 * g4)))
                               * (1.0f / 3.0f));

        S1 += d1; S2 += d2; S3 += d3; S4 += d4;
        V2 += s2; V3 += s3; V4 += s4;
    }

    // combine the 15 threads sharing each joint (SMEM atomics)
    atomicAdd(&spart[jidx * NACC + 0], S1);
    atomicAdd(&spart[jidx * NACC + 1], S2);
    atomicAdd(&spart[jidx * NACC + 2], S3);
    atomicAdd(&spart[jidx * NACC + 3], S4);
    atomicAdd(&spart[jidx * NACC + 4], V2);
    atomicAdd(&spart[jidx * NACC + 5], V3);
    atomicAdd(&spart[jidx * NACC + 6], V4);
    __syncthreads();

    // publish this split's partial
    if (tid < PARTB) g_scratch[b][s][tid] = spart[tid];
    __threadfence();
    __syncthreads();

    if (tid == 0) {
        unsigned old = atomicAdd(&g_ticket[b], 1u);
        s_last = (old == SPLIT - 1);
        if (s_last) g_ticket[b] = 0;   // self-reset for next graph replay
    }
    __syncthreads();

    if (s_last) {
        __threadfence();
        if (tid < PARTB) {
            float sum = 0.0f;
#pragma unroll
            for (int k = 0; k < SPLIT; ++k)
                sum += g_scratch[b][k][tid];
            sfin[tid] = sum;
        }
        __syncthreads();
        if (tid < OUTB) {
            const int j = tid / FEAT;
            const int f = tid % FEAT;
            const float* a = &sfin[j * NACC];
            const float t1 = a[0], t2 = a[1], t3 = a[2], t4 = a[3];
            float v;
            switch (f) {
                case 0: v = (t1 + t2) * 0.5f;               break;
                case 1: v = a[4];                           break;
                case 2: v = t1;                             break;
                case 3: v = (t1 + t2 + t3) * (1.f / 3.f);   break;
                case 4: v = a[5];                           break;
                case 5: v = t1;                             break;
                case 6: v = (t1 + t2 + t3 + t4) * 0.25f;    break;
                case 7: v = a[6];                           break;
                default: v = t1;                            break;
            }
            out[(size_t)b * OUTB + tid] = v * (1.0f / (float)T_DIM);
        }
    }
}

extern "C" void kernel_launch(void* const* d_in, const int* in_sizes, int n_in,
                              void* d_out, int out_size) {
    const float* x = (const float*)d_in[0];
    float* out = (float*)d_out;
    dim3 grid(B_DIM, SPLIT);
    knn_feat_kernel<<<grid, TPB>>>(x, out);
}

// round 14
// speedup vs baseline: 1.1503x; 1.1503x over previous
#include <cuda_runtime.h>
#include <cuda_fp16.h>
#include <math.h>
#include <float.h>

#define B_DIM  256
#define T_DIM  150
#define J_DIM  25
#define FEAT   9
#define NACC   7
#define SPLIT  3
#define TCHUNK (T_DIM / SPLIT)          // 50 timesteps per block
#define NPAIR  (TCHUNK / 2)             // 25 timestep-pairs (lanes t, t+25)
#define ACTIVE (NPAIR * J_DIM)          // 625 compute threads
#define TPB    640                      // 20 full warps
#define ITEMS  (TCHUNK * J_DIM)         // 1250
#define OUTB   (J_DIM * FEAT)           // 225
#define PARTB  (J_DIM * NACC)           // 175

__device__ float    g_scratch[B_DIM][SPLIT][PARTB];
__device__ unsigned g_ticket[B_DIM];    // zero-init; self-resetting

__device__ __forceinline__ float asqrt(float x) {
    float r;
    asm("sqrt.approx.f32 %0, %1;" : "=f"(r) : "f"(x));
    return r;
}

__global__ __launch_bounds__(TPB)
void knn_feat_kernel(const float* __restrict__ x, float* __restrict__ out) {
    // packed positions: [pair][joint] = {x2, y2, z2, pad} (half2 lanes = t, t+25)
    __shared__ uint4 sq[NPAIR][J_DIM];       // 25*25*16 = 10000 B
    __shared__ float spart[PARTB];
    __shared__ float sfin[PARTB];
    __shared__ bool  s_last;

    const int b   = blockIdx.x;
    const int s   = blockIdx.y;
    const int tid = threadIdx.x;

    // build packed half2 SMEM tile (R8-proven form)
    const float* xb = x + ((size_t)b * T_DIM + s * TCHUNK) * (J_DIM * 3);
#pragma unroll
    for (int r = 0; r < 2; ++r) {
        int i = tid + r * TPB;               // 0..1249 : (t, j) item
        if (i < ITEMS) {
            int t = i / J_DIM;               // 0..49
            int j = i % J_DIM;
            int pr = t % NPAIR;              // pair row
            int hi = t / NPAIR;              // 0 = lo half, 1 = hi half
            __half hx = __float2half_rn(xb[3 * i + 0]);
            __half hy = __float2half_rn(xb[3 * i + 1]);
            __half hz = __float2half_rn(xb[3 * i + 2]);
            __half* base = (__half*)&sq[pr][j];
            base[0 * 2 + hi] = hx;
            base[1 * 2 + hi] = hy;
            base[2 * 2 + hi] = hz;
        }
    }
    if (tid < PARTB) spart[tid] = 0.0f;
    __syncthreads();

    if (tid < ACTIVE) {
        const int jidx = tid % J_DIM;        // this thread's joint
        const int pr   = tid / J_DIM;        // timestep pair (0..24)

        // query position (both halves) — one LDS.128
        const uint4 P = sq[pr][jidx];
        const __half2 px = *(const __half2*)&P.x;
        const __half2 py = *(const __half2*)&P.y;
        const __half2 pz = *(const __half2*)&P.z;

        const unsigned inf_bits = 0x7C007C00u;   // (+inf, +inf)
        const __half2 inf2 = *(const __half2*)&inf_bits;

        __half2 m0 = inf2, m1 = inf2, m2 = inf2, m3 = inf2;

#pragma unroll
        for (int j = 0; j < J_DIM; ++j) {
            const uint4 Q = sq[pr][j];       // broadcast LDS.128, feeds 2 candidates
            const __half2 qx = *(const __half2*)&Q.x;
            const __half2 qy = *(const __half2*)&Q.y;
            const __half2 qz = *(const __half2*)&Q.z;

            const __half2 dx = __hsub2(px, qx);
            const __half2 dy = __hsub2(py, qy);
            const __half2 dz = __hsub2(pz, qz);
            __half2 g = __hfma2(dx, dx, __hfma2(dy, dy, __hmul2(dz, dz)));
            g = (j == jidx) ? inf2 : g;      // mask self (both halves)

            __half2 h;
            h = __hmax2(g, m0); m0 = __hmin2(g, m0); g = h;
            h = __hmax2(g, m1); m1 = __hmin2(g, m1); g = h;
            h = __hmax2(g, m2); m2 = __hmin2(g, m2); g = h;
            m3 = __hmin2(g, m3);
        }

        // epilogue: two chains (lo/hi halves), features in fp32, summed
        float S1 = 0.f, S2 = 0.f, S3 = 0.f, S4 = 0.f;
        float V2 = 0.f, V3 = 0.f, V4 = 0.f;

#pragma unroll
        for (int h = 0; h < 2; ++h) {
            const float q0 = h ? __high2float(m0) : __low2float(m0);
            const float q1 = h ? __high2float(m1) : __low2float(m1);
            const float q2 = h ? __high2float(m2) : __low2float(m2);
            const float q3 = h ? __high2float(m3) : __low2float(m3);

            const float d1 = asqrt(q0);
            const float d2 = asqrt(q1);
            const float d3 = asqrt(q2);
            const float d4 = asqrt(q3);

            const float s2 = fabsf(d2 - d1) * 0.70710678118654752f;
            const float a3 = (d1 + d2 + d3) * (1.0f / 3.0f);
            const float e1 = d1 - a3, e2 = d2 - a3, e3 = d3 - a3;
            const float s3 = asqrt(fmaf(e1, e1, fmaf(e2, e2, e3 * e3)) * 0.5f);
            const float a4 = (d1 + d2 + d3 + d4) * 0.25f;
            const float g1 = d1 - a4, g2 = d2 - a4, g3 = d3 - a4, g4 = d4 - a4;
            const float s4 = asqrt(fmaf(g1, g1, fmaf(g2, g2, fmaf(g3, g3, g4 * g4)))
                                   * (1.0f / 3.0f));

            S1 += d1; S2 += d2; S3 += d3; S4 += d4;
            V2 += s2; V3 += s3; V4 += s4;
        }

        // combine the 25 threads sharing each joint (SMEM atomics)
        atomicAdd(&spart[jidx * NACC + 0], S1);
        atomicAdd(&spart[jidx * NACC + 1], S2);
        atomicAdd(&spart[jidx * NACC + 2], S3);
        atomicAdd(&spart[jidx * NACC + 3], S4);
        atomicAdd(&spart[jidx * NACC + 4], V2);
        atomicAdd(&spart[jidx * NACC + 5], V3);
        atomicAdd(&spart[jidx * NACC + 6], V4);
    }
    __syncthreads();

    // publish this split's partial
    if (tid < PARTB) g_scratch[b][s][tid] = spart[tid];
    __threadfence();
    __syncthreads();

    if (tid == 0) {
        unsigned old = atomicAdd(&g_ticket[b], 1u);
        s_last = (old == SPLIT - 1);
        if (s_last) g_ticket[b] = 0;   // self-reset for next graph replay
    }
    __syncthreads();

    if (s_last) {
        __threadfence();
        if (tid < PARTB) {
            float sum = 0.0f;
#pragma unroll
            for (int k = 0; k < SPLIT; ++k)
                sum += g_scratch[b][k][tid];
            sfin[tid] = sum;
        }
        __syncthreads();
        if (tid < OUTB) {
            const int j = tid / FEAT;
            const int f = tid % FEAT;
            const float* a = &sfin[j * NACC];
            const float t1 = a[0], t2 = a[1], t3 = a[2], t4 = a[3];
            float v;
            switch (f) {
                case 0: v = (t1 + t2) * 0.5f;               break;
                case 1: v = a[4];                           break;
                case 2: v = t1;                             break;
                case 3: v = (t1 + t2 + t3) * (1.f / 3.f);   break;
                case 4: v = a[5];                           break;
                case 5: v = t1;                             break;
                case 6: v = (t1 + t2 + t3 + t4) * 0.25f;    break;
                case 7: v = a[6];                           break;
                default: v = t1;                            break;
            }
            out[(size_t)b * OUTB + tid] = v * (1.0f / (float)T_DIM);
        }
    }
}

extern "C" void kernel_launch(void* const* d_in, const int* in_sizes, int n_in,
                              void* d_out, int out_size) {
    const float* x = (const float*)d_in[0];
    float* out = (float*)d_out;
    dim3 grid(B_DIM, SPLIT);
    knn_feat_kernel<<<grid, TPB>>>(x, out);
}

// round 15
// speedup vs baseline: 1.1635x; 1.0115x over previous
#include <cuda_runtime.h>
#include <cuda_fp16.h>
#include <math.h>
#include <float.h>

#define B_DIM  256
#define T_DIM  150
#define J_DIM  25
#define FEAT   9
#define NACC   7
#define SPLIT  3
#define TCHUNK (T_DIM / SPLIT)          // 50 timesteps per block
#define NPAIR  (TCHUNK / 2)             // 25 timestep-pairs (lanes t, t+25)
#define ACTIVE (NPAIR * J_DIM)          // 625 compute threads
#define TPB    640                      // 20 full warps
#define ITEMS  (TCHUNK * J_DIM)         // 1250
#define OUTB   (J_DIM * FEAT)           // 225
#define PARTB  (J_DIM * NACC)           // 175

__device__ float    g_scratch[B_DIM][SPLIT][PARTB];
__device__ unsigned g_ticket[B_DIM];    // zero-init; self-resetting

__device__ __forceinline__ float asqrt(float x) {
    float r;
    asm("sqrt.approx.f32 %0, %1;" : "=f"(r) : "f"(x));
    return r;
}

__global__ __launch_bounds__(TPB)
void knn_feat_kernel(const float* __restrict__ x, float* __restrict__ out) {
    // packed positions: [pair][joint] = {x2, y2, z2, pad} (half2 lanes = t, t+25)
    __shared__ uint4 sq[NPAIR][J_DIM];       // 25*25*16 = 10000 B
    __shared__ float spart[PARTB];
    __shared__ float sfin[PARTB];
    __shared__ bool  s_last;

    const int b   = blockIdx.x;
    const int s   = blockIdx.y;
    const int tid = threadIdx.x;

    // build packed half2 SMEM tile (R8-proven form)
    const float* xb = x + ((size_t)b * T_DIM + s * TCHUNK) * (J_DIM * 3);
#pragma unroll
    for (int r = 0; r < 2; ++r) {
        int i = tid + r * TPB;               // 0..1249 : (t, j) item
        if (i < ITEMS) {
            int t = i / J_DIM;               // 0..49
            int j = i % J_DIM;
            int pr = t % NPAIR;              // pair row
            int hi = t / NPAIR;              // 0 = lo half, 1 = hi half
            __half hx = __float2half_rn(xb[3 * i + 0]);
            __half hy = __float2half_rn(xb[3 * i + 1]);
            __half hz = __float2half_rn(xb[3 * i + 2]);
            __half* base = (__half*)&sq[pr][j];
            base[0 * 2 + hi] = hx;
            base[1 * 2 + hi] = hy;
            base[2 * 2 + hi] = hz;
        }
    }
    if (tid < PARTB) spart[tid] = 0.0f;
    __syncthreads();

    if (tid < ACTIVE) {
        const int jidx = tid % J_DIM;        // this thread's joint
        const int pr   = tid / J_DIM;        // timestep pair (0..24)

        // query position (both halves) — one LDS.128
        const uint4 P = sq[pr][jidx];
        const __half2 px = *(const __half2*)&P.x;
        const __half2 py = *(const __half2*)&P.y;
        const __half2 pz = *(const __half2*)&P.z;

        const unsigned inf_bits = 0x7C007C00u;   // (+inf, +inf)
        const __half2 inf2 = *(const __half2*)&inf_bits;

        __half2 m0 = inf2, m1 = inf2, m2 = inf2, m3 = inf2;

#pragma unroll
        for (int j = 0; j < J_DIM; ++j) {
            const uint4 Q = sq[pr][j];       // broadcast LDS.128, feeds 2 candidates
            const __half2 qx = *(const __half2*)&Q.x;
            const __half2 qy = *(const __half2*)&Q.y;
            const __half2 qz = *(const __half2*)&Q.z;

            const __half2 dx = __hsub2(px, qx);
            const __half2 dy = __hsub2(py, qy);
            const __half2 dz = __hsub2(pz, qz);
            __half2 g = __hfma2(dx, dx, __hfma2(dy, dy, __hmul2(dz, dz)));
            g = (j == jidx) ? inf2 : g;      // mask self (both halves)

            __half2 h;
            h = __hmax2(g, m0); m0 = __hmin2(g, m0); g = h;
            h = __hmax2(g, m1); m1 = __hmin2(g, m1); g = h;
            h = __hmax2(g, m2); m2 = __hmin2(g, m2); g = h;
            m3 = __hmin2(g, m3);
        }

        // epilogue: two chains (lo/hi halves), features in fp32, summed
        float S1 = 0.f, S2 = 0.f, S3 = 0.f, S4 = 0.f;
        float V2 = 0.f, V3 = 0.f, V4 = 0.f;

#pragma unroll
        for (int h = 0; h < 2; ++h) {
            const float q0 = h ? __high2float(m0) : __low2float(m0);
            const float q1 = h ? __high2float(m1) : __low2float(m1);
            const float q2 = h ? __high2float(m2) : __low2float(m2);
            const float q3 = h ? __high2float(m3) : __low2float(m3);

            const float d1 = asqrt(q0);
            const float d2 = asqrt(q1);
            const float d3 = asqrt(q2);
            const float d4 = asqrt(q3);

            const float s2 = fabsf(d2 - d1) * 0.70710678118654752f;
            const float a3 = (d1 + d2 + d3) * (1.0f / 3.0f);
            const float e1 = d1 - a3, e2 = d2 - a3, e3 = d3 - a3;
            const float s3 = asqrt(fmaf(e1, e1, fmaf(e2, e2, e3 * e3)) * 0.5f);
            const float a4 = (d1 + d2 + d3 + d4) * 0.25f;
            const float g1 = d1 - a4, g2 = d2 - a4, g3 = d3 - a4, g4 = d4 - a4;
            const float s4 = asqrt(fmaf(g1, g1, fmaf(g2, g2, fmaf(g3, g3, g4 * g4)))
                                   * (1.0f / 3.0f));

            S1 += d1; S2 += d2; S3 += d3; S4 += d4;
            V2 += s2; V3 += s3; V4 += s4;
        }

        // combine the 25 threads sharing each joint (SMEM atomics)
        atomicAdd(&spart[jidx * NACC + 0], S1);
        atomicAdd(&spart[jidx * NACC + 1], S2);
        atomicAdd(&spart[jidx * NACC + 2], S3);
        atomicAdd(&spart[jidx * NACC + 3], S4);
        atomicAdd(&spart[jidx * NACC + 4], V2);
        atomicAdd(&spart[jidx * NACC + 5], V3);
        atomicAdd(&spart[jidx * NACC + 6], V4);
    }
    __syncthreads();

    // publish this split's partial
    if (tid < PARTB) g_scratch[b][s][tid] = spart[tid];
    __threadfence();
    __syncthreads();

    if (tid == 0) {
        unsigned old = atomicAdd(&g_ticket[b], 1u);
        s_last = (old == SPLIT - 1);
        if (s_last) g_ticket[b] = 0;   // self-reset for next graph replay
    }
    __syncthreads();

    if (s_last) {
        __threadfence();
        if (tid < PARTB) {
            float sum = 0.0f;
#pragma unroll
            for (int k = 0; k < SPLIT; ++k)
                sum += g_scratch[b][k][tid];
            sfin[tid] = sum;
        }
        __syncthreads();
        if (tid < OUTB) {
            const int j = tid / FEAT;
            const int f = tid % FEAT;
            const float* a = &sfin[j * NACC];
            const float t1 = a[0], t2 = a[1], t3 = a[2], t4 = a[3];
            float v;
            switch (f) {
                case 0: v = (t1 + t2) * 0.5f;               break;
                case 1: v = a[4];                           break;
                case 2: v = t1;                             break;
                case 3: v = (t1 + t2 + t3) * (1.f / 3.f);   break;
                case 4: v = a[5];                           break;
                case 5: v = t1;                             break;
                case 6: v = (t1 + t2 + t3 + t4) * 0.25f;    break;
                case 7: v = a[6];                           break;
                default: v = t1;                            break;
            }
            out[(size_t)b * OUTB + tid] = v * (1.0f / (float)T_DIM);
        }
    }
}

extern "C" void kernel_launch(void* const* d_in, const int* in_sizes, int n_in,
                              void* d_out, int out_size) {
    const float* x = (const float*)d_in[0];
    float* out = (float*)d_out;
    dim3 grid(B_DIM, SPLIT);
    knn_feat_kernel<<<grid, TPB>>>(x, out);
}

// round 16
// speedup vs baseline: 1.4190x; 1.2196x over previous
#include <cuda_runtime.h>
#include <cuda_fp16.h>
#include <math.h>
#include <float.h>

#define B_DIM  256
#define T_DIM  150
#define J_DIM  25
#define FEAT   9
#define NACC   7
#define SPLIT  5
#define TCHUNK (T_DIM / SPLIT)          // 30 timesteps per block
#define NPAIR  (TCHUNK / 2)             // 15 timestep-pairs
#define TPB    (NPAIR * J_DIM)          // 375 threads; thread = (pair, joint)
#define ITEMS  (TCHUNK * J_DIM)         // 750
#define OUTB   (J_DIM * FEAT)           // 225
#define PARTB  (J_DIM * NACC)           // 175

__device__ float    g_scratch[B_DIM][SPLIT][PARTB];
__device__ unsigned g_ticket[B_DIM];    // zero-init; self-resetting

__device__ __forceinline__ float asqrt(float x) {
    float r;
    asm("sqrt.approx.f32 %0, %1;" : "=f"(r) : "f"(x));
    return r;
}

__global__ __launch_bounds__(TPB, 5)
void knn_feat_kernel(const float* __restrict__ x, float* __restrict__ out) {
    // packed positions: [pair][joint] = {x2, y2, z2, pad} (half2 lanes = t, t+15)
    __shared__ uint4 sq[NPAIR][J_DIM];       // 15*25*16 = 6000 B
    __shared__ float spart[PARTB];
    __shared__ float sfin[PARTB];
    __shared__ bool  s_last;

    const int b   = blockIdx.x;
    const int s   = blockIdx.y;
    const int tid = threadIdx.x;

    // build packed half2 SMEM tile
    const float* xb = x + ((size_t)b * T_DIM + s * TCHUNK) * (J_DIM * 3);
#pragma unroll
    for (int r = 0; r < 2; ++r) {
        int i = tid + r * TPB;               // 0..749 : (t, j) item
        int t = i / J_DIM;                   // 0..29
        int j = i % J_DIM;
        int pr = t % NPAIR;                  // pair row
        int hi = t / NPAIR;                  // 0 = lo half, 1 = hi half
        __half hx = __float2half_rn(xb[3 * i + 0]);
        __half hy = __float2half_rn(xb[3 * i + 1]);
        __half hz = __float2half_rn(xb[3 * i + 2]);
        __half* base = (__half*)&sq[pr][j];
        base[0 * 2 + hi] = hx;
        base[1 * 2 + hi] = hy;
        base[2 * 2 + hi] = hz;
    }
    if (tid < PARTB) spart[tid] = 0.0f;
    __syncthreads();

    const int jidx = tid % J_DIM;            // this thread's joint
    const int pr   = tid / J_DIM;            // this thread's timestep pair (0..14)

    // query position (both halves) — one LDS.128
    const uint4 P = sq[pr][jidx];
    const __half2 px = *(const __half2*)&P.x;
    const __half2 py = *(const __half2*)&P.y;
    const __half2 pz = *(const __half2*)&P.z;

    const unsigned inf_bits = 0x7C007C00u;   // (+inf, +inf)
    const __half2 inf2 = *(const __half2*)&inf_bits;

    __half2 m0 = inf2, m1 = inf2, m2 = inf2, m3 = inf2;

#pragma unroll
    for (int j = 0; j < J_DIM; ++j) {
        const uint4 Q = sq[pr][j];           // broadcast LDS.128, feeds 2 candidates
        const __half2 qx = *(const __half2*)&Q.x;
        const __half2 qy = *(const __half2*)&Q.y;
        const __half2 qz = *(const __half2*)&Q.z;

        const __half2 dx = __hsub2(px, qx);
        const __half2 dy = __hsub2(py, qy);
        const __half2 dz = __hsub2(pz, qz);
        __half2 g = __hfma2(dx, dx, __hfma2(dy, dy, __hmul2(dz, dz)));
        g = (j == jidx) ? inf2 : g;          // mask self (both halves)

        __half2 h;
        h = __hmax2(g, m0); m0 = __hmin2(g, m0); g = h;
        h = __hmax2(g, m1); m1 = __hmin2(g, m1); g = h;
        h = __hmax2(g, m2); m2 = __hmin2(g, m2); g = h;
        m3 = __hmin2(g, m3);
    }

    // epilogue: two chains (lo/hi halves), features in fp32, summed
    float S1 = 0.f, S2 = 0.f, S3 = 0.f, S4 = 0.f;
    float V2 = 0.f, V3 = 0.f, V4 = 0.f;

#pragma unroll
    for (int h = 0; h < 2; ++h) {
        const float q0 = h ? __high2float(m0) : __low2float(m0);
        const float q1 = h ? __high2float(m1) : __low2float(m1);
        const float q2 = h ? __high2float(m2) : __low2float(m2);
        const float q3 = h ? __high2float(m3) : __low2float(m3);

        const float d1 = asqrt(q0);
        const float d2 = asqrt(q1);
        const float d3 = asqrt(q2);
        const float d4 = asqrt(q3);

        const float s2 = fabsf(d2 - d1) * 0.70710678118654752f;
        const float a3 = (d1 + d2 + d3) * (1.0f / 3.0f);
        const float e1 = d1 - a3, e2 = d2 - a3, e3 = d3 - a3;
        const float s3 = asqrt(fmaf(e1, e1, fmaf(e2, e2, e3 * e3)) * 0.5f);
        const float a4 = (d1 + d2 + d3 + d4) * 0.25f;
        const float g1 = d1 - a4, g2 = d2 - a4, g3 = d3 - a4, g4 = d4 - a4;
        const float s4 = asqrt(fmaf(g1, g1, fmaf(g2, g2, fmaf(g3, g3, g4 * g4)))
                               * (1.0f / 3.0f));

        S1 += d1; S2 += d2; S3 += d3; S4 += d4;
        V2 += s2; V3 += s3; V4 += s4;
    }

    // combine the 15 threads sharing each joint (SMEM atomics)
    atomicAdd(&spart[jidx * NACC + 0], S1);
    atomicAdd(&spart[jidx * NACC + 1], S2);
    atomicAdd(&spart[jidx * NACC + 2], S3);
    atomicAdd(&spart[jidx * NACC + 3], S4);
    atomicAdd(&spart[jidx * NACC + 4], V2);
    atomicAdd(&spart[jidx * NACC + 5], V3);
    atomicAdd(&spart[jidx * NACC + 6], V4);
    __syncthreads();

    // publish this split's partial
    if (tid < PARTB) g_scratch[b][s][tid] = spart[tid];
    __threadfence();
    __syncthreads();

    if (tid == 0) {
        unsigned old = atomicAdd(&g_ticket[b], 1u);
        s_last = (old == SPLIT - 1);
        if (s_last) g_ticket[b] = 0;   // self-reset for next graph replay
    }
    __syncthreads();

    if (s_last) {
        __threadfence();
        if (tid < PARTB) {
            float sum = 0.0f;
#pragma unroll
            for (int k = 0; k < SPLIT; ++k)
                sum += g_scratch[b][k][tid];
            sfin[tid] = sum;
        }
        __syncthreads();
        if (tid < OUTB) {
            const int j = tid / FEAT;
            const int f = tid % FEAT;
            const float* a = &sfin[j * NACC];
            const float t1 = a[0], t2 = a[1], t3 = a[2], t4 = a[3];
            float v;
            switch (f) {
                case 0: v = (t1 + t2) * 0.5f;               break;
                case 1: v = a[4];                           break;
                case 2: v = t1;                             break;
                case 3: v = (t1 + t2 + t3) * (1.f / 3.f);   break;
                case 4: v = a[5];                           break;
                case 5: v = t1;                             break;
                case 6: v = (t1 + t2 + t3 + t4) * 0.25f;    break;
                case 7: v = a[6];                           break;
                default: v = t1;                            break;
            }
            out[(size_t)b * OUTB + tid] = v * (1.0f / (float)T_DIM);
        }
    }
}

extern "C" void kernel_launch(void* const* d_in, const int* in_sizes, int n_in,
                              void* d_out, int out_size) {
    const float* x = (const float*)d_in[0];
    float* out = (float*)d_out;
    dim3 grid(B_DIM, SPLIT);
    knn_feat_kernel<<<grid, TPB>>>(x, out);
}

// round 17
// speedup vs baseline: 1.7254x; 1.2159x over previous
#include <cuda_runtime.h>
#include <cuda_fp16.h>
#include <math.h>
#include <float.h>

#define B_DIM  256
#define T_DIM  150
#define J_DIM  25
#define FEAT   9
#define NACC   7
#define SPLIT  5
#define TCHUNK (T_DIM / SPLIT)          // 30 timesteps per block
#define NPAIR  (TCHUNK / 2)             // 15 timestep-pairs
#define TPB    (NPAIR * J_DIM)          // 375 threads; thread = (pair, joint)
#define ITEMS  (TCHUNK * J_DIM)         // 750
#define OUTB   (J_DIM * FEAT)           // 225
#define PARTB  (J_DIM * NACC)           // 175

__device__ float    g_scratch[B_DIM][SPLIT][PARTB];
__device__ unsigned g_ticket[B_DIM];    // zero-init; self-resetting

__device__ __forceinline__ float asqrt(float x) {
    float r;
    asm("sqrt.approx.f32 %0, %1;" : "=f"(r) : "f"(x));
    return r;
}

__global__ __launch_bounds__(TPB, 5)
void knn_feat_kernel(const float* __restrict__ x, float* __restrict__ out) {
    // packed positions: [pair][joint] = {x2, y2, z2, pad} (half2 lanes = t, t+15)
    __shared__ uint4 sq[NPAIR][J_DIM];       // 6000 B
    __shared__ float spred[NPAIR][PARTB];    // per-(pair,joint) partials, 10500 B
    __shared__ float sfin[PARTB];
    __shared__ bool  s_last;

    const int b   = blockIdx.x;
    const int s   = blockIdx.y;
    const int tid = threadIdx.x;

    // build packed half2 SMEM tile
    const float* xb = x + ((size_t)b * T_DIM + s * TCHUNK) * (J_DIM * 3);
#pragma unroll
    for (int r = 0; r < 2; ++r) {
        int i = tid + r * TPB;               // 0..749 : (t, j) item
        int t = i / J_DIM;                   // 0..29
        int j = i % J_DIM;
        int pr = t % NPAIR;                  // pair row
        int hi = t / NPAIR;                  // 0 = lo half, 1 = hi half
        __half hx = __float2half_rn(xb[3 * i + 0]);
        __half hy = __float2half_rn(xb[3 * i + 1]);
        __half hz = __float2half_rn(xb[3 * i + 2]);
        __half* base = (__half*)&sq[pr][j];
        base[0 * 2 + hi] = hx;
        base[1 * 2 + hi] = hy;
        base[2 * 2 + hi] = hz;
    }
    __syncthreads();

    const int jidx = tid % J_DIM;            // this thread's joint
    const int pr   = tid / J_DIM;            // this thread's timestep pair (0..14)

    // query position (both halves) — one LDS.128
    const uint4 P = sq[pr][jidx];
    const __half2 px = *(const __half2*)&P.x;
    const __half2 py = *(const __half2*)&P.y;
    const __half2 pz = *(const __half2*)&P.z;

    const unsigned inf_bits = 0x7C007C00u;   // (+inf, +inf)
    const __half2 inf2 = *(const __half2*)&inf_bits;

    __half2 m0 = inf2, m1 = inf2, m2 = inf2, m3 = inf2;

#pragma unroll
    for (int j = 0; j < J_DIM; ++j) {
        const uint4 Q = sq[pr][j];           // broadcast LDS.128, feeds 2 candidates
        const __half2 qx = *(const __half2*)&Q.x;
        const __half2 qy = *(const __half2*)&Q.y;
        const __half2 qz = *(const __half2*)&Q.z;

        const __half2 dx = __hsub2(px, qx);
        const __half2 dy = __hsub2(py, qy);
        const __half2 dz = __hsub2(pz, qz);
        __half2 g = __hfma2(dx, dx, __hfma2(dy, dy, __hmul2(dz, dz)));
        g = (j == jidx) ? inf2 : g;          // mask self (both halves)

        __half2 h;
        h = __hmax2(g, m0); m0 = __hmin2(g, m0); g = h;
        h = __hmax2(g, m1); m1 = __hmin2(g, m1); g = h;
        h = __hmax2(g, m2); m2 = __hmin2(g, m2); g = h;
        m3 = __hmin2(g, m3);
    }

    // epilogue: two chains (lo/hi halves), features in fp32, summed
    float S1 = 0.f, S2 = 0.f, S3 = 0.f, S4 = 0.f;
    float V2 = 0.f, V3 = 0.f, V4 = 0.f;

#pragma unroll
    for (int h = 0; h < 2; ++h) {
        const float q0 = h ? __high2float(m0) : __low2float(m0);
        const float q1 = h ? __high2float(m1) : __low2float(m1);
        const float q2 = h ? __high2float(m2) : __low2float(m2);
        const float q3 = h ? __high2float(m3) : __low2float(m3);

        const float d1 = asqrt(q0);
        const float d2 = asqrt(q1);
        const float d3 = asqrt(q2);
        const float d4 = asqrt(q3);

        const float s2 = fabsf(d2 - d1) * 0.70710678118654752f;
        const float a3 = (d1 + d2 + d3) * (1.0f / 3.0f);
        const float e1 = d1 - a3, e2 = d2 - a3, e3 = d3 - a3;
        const float s3 = asqrt(fmaf(e1, e1, fmaf(e2, e2, e3 * e3)) * 0.5f);
        const float a4 = (d1 + d2 + d3 + d4) * 0.25f;
        const float g1 = d1 - a4, g2 = d2 - a4, g3 = d3 - a4, g4 = d4 - a4;
        const float s4 = asqrt(fmaf(g1, g1, fmaf(g2, g2, fmaf(g3, g3, g4 * g4)))
                               * (1.0f / 3.0f));

        S1 += d1; S2 += d2; S3 += d3; S4 += d4;
        V2 += s2; V3 += s3; V4 += s4;
    }

    // contention-free: each (pr, jidx) thread owns a unique SMEM slot (no atomics)
    {
        float* sp = &spred[pr][jidx * NACC];
        sp[0] = S1; sp[1] = S2; sp[2] = S3; sp[3] = S4;
        sp[4] = V2; sp[5] = V3; sp[6] = V4;
    }
    __syncthreads();

    // transposed reduce over the 15 pair-rows, publish this split's partial
    if (tid < PARTB) {
        float sum = 0.0f;
#pragma unroll
        for (int k = 0; k < NPAIR; ++k)
            sum += spred[k][tid];
        g_scratch[b][s][tid] = sum;
    }
    __threadfence();
    __syncthreads();

    if (tid == 0) {
        unsigned old = atomicAdd(&g_ticket[b], 1u);
        s_last = (old == SPLIT - 1);
        if (s_last) g_ticket[b] = 0;   // self-reset for next graph replay
    }
    __syncthreads();

    if (s_last) {
        __threadfence();
        if (tid < PARTB) {
            float sum = 0.0f;
#pragma unroll
            for (int k = 0; k < SPLIT; ++k)
                sum += g_scratch[b][k][tid];
            sfin[tid] = sum;
        }
        __syncthreads();
        if (tid < OUTB) {
            const int j = tid / FEAT;
            const int f = tid % FEAT;
            const float* a = &sfin[j * NACC];
            const float t1 = a[0], t2 = a[1], t3 = a[2], t4 = a[3];
            float v;
            switch (f) {
                case 0: v = (t1 + t2) * 0.5f;               break;
                case 1: v = a[4];                           break;
                case 2: v = t1;                             break;
                case 3: v = (t1 + t2 + t3) * (1.f / 3.f);   break;
                case 4: v = a[5];                           break;
                case 5: v = t1;                             break;
                case 6: v = (t1 + t2 + t3 + t4) * 0.25f;    break;
                case 7: v = a[6];                           break;
                default: v = t1;                            break;
            }
            out[(size_t)b * OUTB + tid] = v * (1.0f / (float)T_DIM);
        }
    }
}

extern "C" void kernel_launch(void* const* d_in, const int* in_sizes, int n_in,
                              void* d_out, int out_size) {
    const float* x = (const float*)d_in[0];
    float* out = (float*)d_out;
    dim3 grid(B_DIM, SPLIT);
    knn_feat_kernel<<<grid, TPB>>>(x, out);
}